// round 2
// baseline (speedup 1.0000x reference)
#include <cuda_runtime.h>
#include <cstdint>

// ---------------- Problem constants ----------------
#define Bn 256
#define Tn 128
#define Hn 1024
#define Vn 32
#define Gn 4096              // 4*H
#define BH (Bn*Hn)           // 262144
#define THB (Tn*BH)          // 33554432
#define NW (Gn*Hn)           // 4194304 (one weight matrix)

// ---------------- Device scratch (allocation-free) ----------------
__device__ float g_Whh[3*NW];      // tf32-rounded recurrent weights (layers 0..2)
__device__ float g_Wih[2*NW];      // tf32-rounded input weights (layers 1..2)
__device__ float g_hs[2][THB];     // ping-pong full-precision hidden sequences
__device__ float g_hr[2][BH];      // PING-PONG tf32-rounded h state (GEMM operand)
                                   // read [t&1], write [(t&1)^1] -> no cross-CTA race
__device__ float g_hf[BH];         // full-precision h state (own-range access only)
__device__ float g_c[BH];          // full-precision c state (own-range access only)
__device__ float g_WoutT[Hn*Vn];   // W_out transposed [k][v]

// ---------------- Helpers ----------------
__device__ __forceinline__ float tf32r(float x) {
    uint32_t u;
    asm("cvt.rna.tf32.f32 %0, %1;" : "=r"(u) : "f"(x));
    return __uint_as_float(u);
}

__device__ __forceinline__ void mma_tf32(float* d, const uint32_t* a, const uint32_t* b) {
    asm volatile(
        "mma.sync.aligned.m16n8k8.row.col.f32.tf32.tf32.f32 "
        "{%0,%1,%2,%3},{%4,%5,%6,%7},{%8,%9},{%0,%1,%2,%3};\n"
        : "+f"(d[0]), "+f"(d[1]), "+f"(d[2]), "+f"(d[3])
        : "r"(a[0]), "r"(a[1]), "r"(a[2]), "r"(a[3]), "r"(b[0]), "r"(b[1]));
}

__device__ __forceinline__ float sigmoidf_(float x) {
    return 1.0f / (1.0f + __expf(-x));
}

// ---------------- Prep: round weights to tf32, transpose W_out ----------------
__global__ void prep_kernel(const float* __restrict__ Whh0,
                            const float* __restrict__ Wih_rest,
                            const float* __restrict__ Whh_rest,
                            const float* __restrict__ Wout) {
    int i = blockIdx.x * blockDim.x + threadIdx.x;
    int stride = gridDim.x * blockDim.x;
    for (int idx = i; idx < NW; idx += stride)
        g_Whh[idx] = tf32r(Whh0[idx]);
    for (int idx = i; idx < 2 * NW; idx += stride) {
        g_Whh[NW + idx] = tf32r(Whh_rest[idx]);
        g_Wih[idx]      = tf32r(Wih_rest[idx]);
    }
    for (int idx = i; idx < Hn * Vn; idx += stride) {
        int v = idx >> 10, k = idx & 1023;
        g_WoutT[k * Vn + v] = Wout[idx];
    }
}

// ---------------- Zero h/c state at layer start ----------------
__global__ void zero_state() {
    int i = blockIdx.x * blockDim.x + threadIdx.x;
    if (i < BH) { g_hr[0][i] = 0.f; g_hr[1][i] = 0.f; g_hf[i] = 0.f; g_c[i] = 0.f; }
}

// ---------------- One LSTM timestep ----------------
// grid (64, 2): blockIdx.x = hidden-slice (16 cols across all 4 gate groups),
//               blockIdx.y = batch half (128 rows). 256 threads, 8 warps (4M x 2N).
// CTA GEMM tile: 128(M=batch) x 64(N=gate cols) x K (1024 or 2048 when x folded).
template<bool HASX>
__global__ void __launch_bounds__(256) lstm_step(int layer, int t,
                                                 const float* __restrict__ bias,
                                                 const float* __restrict__ Wih0,
                                                 const int* __restrict__ tokens,
                                                 const int* __restrict__ lengths) {
    __shared__ float sm[8704];          // union: A[128][36]+B[64][36]  |  gates[128][68]
    float* sA = sm;                     // [128][36]
    float* sB = sm + 128 * 36;          // [64][36]

    const int tid  = threadIdx.x;
    const int lane = tid & 31, wid = tid >> 5;
    const int wm = wid & 3, wn = wid >> 2;        // warp tile: 32x32
    const int gid = lane >> 2, tig = lane & 3;    // mma fragment ids
    const int jbase = blockIdx.x * 16;            // hidden slice
    const int mBase = blockIdx.y * 128;           // batch half

    const float* Whh  = g_Whh + (size_t)layer * NW;
    const float* Wih  = HASX ? (g_Wih + (size_t)(layer - 1) * NW) : nullptr;
    const float* xseq = HASX ? (g_hs[(layer + 1) & 1] + (size_t)t * BH) : nullptr;
    const float* hrIn = g_hr[t & 1];              // state read buffer
    float*       hrOut = g_hr[(t & 1) ^ 1];       // state write buffer (race-free)
    float* hsout = g_hs[layer & 1] + (size_t)t * BH;

    float acc[2][4][4];
    #pragma unroll
    for (int a0 = 0; a0 < 2; a0++)
        #pragma unroll
        for (int a1 = 0; a1 < 4; a1++)
            #pragma unroll
            for (int a2 = 0; a2 < 4; a2++) acc[a0][a1][a2] = 0.f;

    const int KTOT = HASX ? 2 * Hn : Hn;
    for (int k0 = 0; k0 < KTOT; k0 += 32) {
        const bool hx = (k0 >= Hn);
        const float* Asrc = hx ? (xseq + (size_t)mBase * Hn + (k0 - Hn))
                               : (hrIn + (size_t)mBase * Hn + k0);
        const float* Wsrc = hx ? (Wih + (k0 - Hn)) : (Whh + k0);

        // Stage A tile: 128 rows x 32 k (float4, pad-36 rows keep 16B alignment)
        #pragma unroll
        for (int it = 0; it < 4; it++) {
            int idx = tid + it * 256;
            int r = idx >> 3, c = (idx & 7) * 4;
            float4 v = *reinterpret_cast<const float4*>(Asrc + (size_t)r * Hn + c);
            *reinterpret_cast<float4*>(sA + r * 36 + c) = v;
        }
        // Stage B tile: 64 W rows (4 gate groups x 16 hidden cols) x 32 k
        #pragma unroll
        for (int it = 0; it < 2; it++) {
            int idx = tid + it * 256;
            int r = idx >> 3, c = (idx & 7) * 4;
            int wrow = ((r >> 4) << 10) + jbase + (r & 15);   // group*1024 + j
            float4 v = *reinterpret_cast<const float4*>(Wsrc + (size_t)wrow * Hn + c);
            *reinterpret_cast<float4*>(sB + r * 36 + c) = v;
        }
        __syncthreads();

        #pragma unroll
        for (int kk = 0; kk < 4; kk++) {
            const int kb = kk * 8;
            uint32_t a[2][4];
            #pragma unroll
            for (int mt = 0; mt < 2; mt++) {
                int r0 = wm * 32 + mt * 16 + gid;
                a[mt][0] = __float_as_uint(sA[r0 * 36 + kb + tig]);
                a[mt][1] = __float_as_uint(sA[(r0 + 8) * 36 + kb + tig]);
                a[mt][2] = __float_as_uint(sA[r0 * 36 + kb + tig + 4]);
                a[mt][3] = __float_as_uint(sA[(r0 + 8) * 36 + kb + tig + 4]);
            }
            uint32_t b[4][2];
            #pragma unroll
            for (int nt = 0; nt < 4; nt++) {
                int n0 = wn * 32 + nt * 8 + gid;
                b[nt][0] = __float_as_uint(sB[n0 * 36 + kb + tig]);
                b[nt][1] = __float_as_uint(sB[n0 * 36 + kb + tig + 4]);
            }
            #pragma unroll
            for (int mt = 0; mt < 2; mt++)
                #pragma unroll
                for (int nt = 0; nt < 4; nt++)
                    mma_tf32(acc[mt][nt], a[mt], b[nt]);
        }
        __syncthreads();
    }

    // Exchange gates through smem so each thread sees its i/f/g/o quadruple
    float* gsm = sm;  // [128][68]
    #pragma unroll
    for (int mt = 0; mt < 2; mt++)
        #pragma unroll
        for (int nt = 0; nt < 4; nt++) {
            int r0 = wm * 32 + mt * 16 + gid;
            int c0 = wn * 32 + nt * 8 + tig * 2;
            gsm[r0 * 68 + c0]           = acc[mt][nt][0];
            gsm[r0 * 68 + c0 + 1]       = acc[mt][nt][1];
            gsm[(r0 + 8) * 68 + c0]     = acc[mt][nt][2];
            gsm[(r0 + 8) * 68 + c0 + 1] = acc[mt][nt][3];
        }
    __syncthreads();

    // Pointwise LSTM update with packed-sequence masking
    #pragma unroll
    for (int it = 0; it < 8; it++) {
        int idx = tid + it * 256;          // 2048 (b,j) pairs per CTA
        int bl = idx >> 4, jl = idx & 15;
        int b = mBase + bl;
        int j = jbase + jl;
        float gi = gsm[bl * 68 +      jl] + bias[j];
        float gf = gsm[bl * 68 + 16 + jl] + bias[Hn + j];
        float gg = gsm[bl * 68 + 32 + jl] + bias[2 * Hn + j];
        float go = gsm[bl * 68 + 48 + jl] + bias[3 * Hn + j];
        if (!HASX) {  // layer 0: one-hot input projection == weight-column gather
            int tok = tokens[b * Tn + t];
            gi += Wih0[(size_t)j * Vn + tok];
            gf += Wih0[(size_t)(Hn + j) * Vn + tok];
            gg += Wih0[(size_t)(2 * Hn + j) * Vn + tok];
            go += Wih0[(size_t)(3 * Hn + j) * Vn + tok];
        }
        float si = sigmoidf_(gi);
        float sf = sigmoidf_(gf);
        float tg = tanhf(gg);
        float so = sigmoidf_(go);
        int o = b * Hn + j;
        float cold = g_c[o];
        float cn = sf * cold + si * tg;
        float hn = so * tanhf(cn);
        bool m = (t < lengths[b]);
        float hv = m ? hn : g_hf[o];
        float cv = m ? cn : cold;
        g_c[o]  = cv;
        g_hf[o] = hv;
        hrOut[o] = tf32r(hv);
        hsout[o] = hv;
    }
}

// ---------------- Copy final h/c of a layer into output ----------------
__global__ void copy_final(int layer, float* __restrict__ out) {
    int i = blockIdx.x * blockDim.x + threadIdx.x;
    if (i >= BH) return;
    float* oh = out + (size_t)Bn * Tn * Vn + (size_t)layer * BH;
    float* oc = out + (size_t)Bn * Tn * Vn + (size_t)3 * BH + (size_t)layer * BH;
    const float* hsrc = g_hs[layer & 1] + (size_t)(Tn - 1) * BH;
    oh[i] = hsrc[i];   // h after masked update at t=T-1 == frozen final h
    oc[i] = g_c[i];
}

// ---------------- Output head: logits = hs . W_out^T + b_out (masked) ----------------
__global__ void __launch_bounds__(256) logits_kernel(const float* __restrict__ bout,
                                                     const int* __restrict__ lengths,
                                                     float* __restrict__ out) {
    int gw   = (blockIdx.x * blockDim.x + threadIdx.x) >> 5;  // 0..8191
    int lane = threadIdx.x & 31;                              // lane == vocab index
    const float* hs = g_hs[0];                                // layer-2 output (2&1 == 0)
    int row0 = gw * 4;                                        // rows are (t*256 + b)
    const float* hp = hs + (size_t)row0 * Hn;
    float acc0 = 0.f, acc1 = 0.f, acc2 = 0.f, acc3 = 0.f;

    for (int k0 = 0; k0 < Hn; k0 += 32) {
        float h0 = hp[k0 + lane];
        float h1 = hp[Hn + k0 + lane];
        float h2 = hp[2 * Hn + k0 + lane];
        float h3 = hp[3 * Hn + k0 + lane];
        #pragma unroll
        for (int i = 0; i < 32; i++) {
            float w = g_WoutT[(k0 + i) * Vn + lane];
            acc0 += __shfl_sync(0xffffffffu, h0, i) * w;
            acc1 += __shfl_sync(0xffffffffu, h1, i) * w;
            acc2 += __shfl_sync(0xffffffffu, h2, i) * w;
            acc3 += __shfl_sync(0xffffffffu, h3, i) * w;
        }
    }
    float bo = bout[lane];
    float accs[4] = {acc0, acc1, acc2, acc3};
    #pragma unroll
    for (int r = 0; r < 4; r++) {
        int row = row0 + r;
        int t = row >> 8;       // row = t*256 + b
        int b = row & 255;
        float v = (t < lengths[b]) ? (accs[r] + bo) : 0.f;
        out[((size_t)b * Tn + t) * Vn + lane] = v;
    }
}

// ---------------- Launch ----------------
extern "C" void kernel_launch(void* const* d_in, const int* in_sizes, int n_in,
                              void* d_out, int out_size) {
    const int*   tokens  = (const int*)d_in[0];
    const int*   lengths = (const int*)d_in[1];
    const float* Wih0    = (const float*)d_in[2];
    const float* Whh0    = (const float*)d_in[3];
    const float* b0      = (const float*)d_in[4];
    const float* Wih_r   = (const float*)d_in[5];
    const float* Whh_r   = (const float*)d_in[6];
    const float* b_r     = (const float*)d_in[7];
    const float* Wout    = (const float*)d_in[8];
    const float* bout    = (const float*)d_in[9];
    float* out = (float*)d_out;

    prep_kernel<<<1024, 256>>>(Whh0, Wih_r, Whh_r, Wout);

    dim3 sgrid(64, 2);
    for (int l = 0; l < 3; l++) {
        zero_state<<<1024, 256>>>();
        const float* bias = (l == 0) ? b0 : (b_r + (size_t)(l - 1) * Gn);
        for (int t = 0; t < Tn; t++) {
            if (l == 0) lstm_step<false><<<sgrid, 256>>>(l, t, bias, Wih0, tokens, lengths);
            else        lstm_step<true ><<<sgrid, 256>>>(l, t, bias, Wih0, tokens, lengths);
        }
        copy_final<<<1024, 256>>>(l, out);
    }
    logits_kernel<<<1024, 256>>>(bout, lengths, out);
}

// round 3
// speedup vs baseline: 1.5597x; 1.5597x over previous
#include <cuda_runtime.h>
#include <cstdint>

// ---------------- Problem constants ----------------
#define Bn 256
#define Tn 128
#define Hn 1024
#define Vn 32
#define Gn 4096              // 4*H
#define BH (Bn*Hn)           // 262144
#define THB (Tn*BH)          // 33554432
#define NW (Gn*Hn)           // 4194304 (one weight matrix)
#define MROWS (Tn*Bn)        // 32768 rows of the big input GEMM
#define LOGN (Bn*Tn*Vn)      // 1048576 logits floats

// ---------------- Device scratch (allocation-free) ----------------
__device__ float g_Whh[3*NW];      // tf32-rounded recurrent weights
__device__ float g_Wih[2*NW];      // tf32-rounded input weights (layers 1..2)
__device__ float g_hs[2][THB];     // ping-pong full-precision hidden sequences
__device__ float g_xW[(size_t)MROWS*Gn]; // precomputed input projection (512MB)
__device__ float g_hio[2][BH];     // ping-pong tf32-rounded h (GEMM operand)
__device__ float g_WoutT[Hn*Vn];   // W_out transposed [k][v]
__device__ unsigned g_bar;         // grid barrier counter

// ---------------- Helpers ----------------
__device__ __forceinline__ float tf32r(float x) {
    uint32_t u;
    asm("cvt.rna.tf32.f32 %0, %1;" : "=r"(u) : "f"(x));
    return __uint_as_float(u);
}

__device__ __forceinline__ void mma_tf32(float* d, const uint32_t* a, const uint32_t* b) {
    asm volatile(
        "mma.sync.aligned.m16n8k8.row.col.f32.tf32.tf32.f32 "
        "{%0,%1,%2,%3},{%4,%5,%6,%7},{%8,%9},{%0,%1,%2,%3};\n"
        : "+f"(d[0]), "+f"(d[1]), "+f"(d[2]), "+f"(d[3])
        : "r"(a[0]), "r"(a[1]), "r"(a[2]), "r"(a[3]), "r"(b[0]), "r"(b[1]));
}

__device__ __forceinline__ void cpasync16(float* dst, const float* src) {
    uint32_t d = (uint32_t)__cvta_generic_to_shared(dst);
    asm volatile("cp.async.cg.shared.global [%0], [%1], 16;\n" :: "r"(d), "l"(src));
}

__device__ __forceinline__ float sigmoidf_(float x) {
    return 1.0f / (1.0f + __expf(-x));
}

// ---------------- Prep: round weights to tf32, transpose W_out ----------------
__global__ void prep_kernel(const float* __restrict__ Whh0,
                            const float* __restrict__ Wih_rest,
                            const float* __restrict__ Whh_rest,
                            const float* __restrict__ Wout) {
    int i = blockIdx.x * blockDim.x + threadIdx.x;
    int stride = gridDim.x * blockDim.x;
    for (int idx = i; idx < NW; idx += stride)
        g_Whh[idx] = tf32r(Whh0[idx]);
    for (int idx = i; idx < 2 * NW; idx += stride) {
        g_Whh[NW + idx] = tf32r(Whh_rest[idx]);
        g_Wih[idx]      = tf32r(Wih_rest[idx]);
    }
    for (int idx = i; idx < Hn * Vn; idx += stride) {
        int v = idx >> 10, k = idx & 1023;
        g_WoutT[k * Vn + v] = Wout[idx];
    }
}

// ---------------- Reset h state + barrier before each recurrent phase --------
__global__ void zero_state() {
    int i = blockIdx.x * blockDim.x + threadIdx.x;
    if (i == 0) g_bar = 0;
    if (i < BH) { g_hio[0][i] = 0.f; g_hio[1][i] = 0.f; }
}

// ---------------- Phase A: xW = hs_prev . Wih^T (layers 1..2), no bias -------
// grid (64, 256): bx = 64-col n-tile, by = 128-row m-tile. 256 threads.
__global__ void __launch_bounds__(256) gemmA(int l) {
    __shared__ float sm[8704];          // A[128][36]+B[64][36]  |  out[128][68]
    float* sA = sm;
    float* sB = sm + 128 * 36;

    const int tid  = threadIdx.x;
    const int lane = tid & 31, wid = tid >> 5;
    const int wm = wid & 3, wn = wid >> 2;
    const int gid = lane >> 2, tig = lane & 3;
    const int nbase = blockIdx.x * 64;
    const int mb = blockIdx.y * 128;

    const float* A  = g_hs[(l - 1) & 1] + (size_t)mb * Hn;
    const float* Bw = g_Wih + (size_t)(l - 1) * NW;

    float acc[2][4][4];
    #pragma unroll
    for (int a0 = 0; a0 < 2; a0++)
        #pragma unroll
        for (int a1 = 0; a1 < 4; a1++)
            #pragma unroll
            for (int a2 = 0; a2 < 4; a2++) acc[a0][a1][a2] = 0.f;

    for (int k0 = 0; k0 < Hn; k0 += 32) {
        #pragma unroll
        for (int it = 0; it < 4; it++) {
            int idx = tid + it * 256;
            int r = idx >> 3, c = (idx & 7) * 4;
            float4 v = *reinterpret_cast<const float4*>(A + (size_t)r * Hn + k0 + c);
            *reinterpret_cast<float4*>(sA + r * 36 + c) = v;
        }
        #pragma unroll
        for (int it = 0; it < 2; it++) {
            int idx = tid + it * 256;
            int r = idx >> 3, c = (idx & 7) * 4;
            float4 v = *reinterpret_cast<const float4*>(Bw + (size_t)(nbase + r) * Hn + k0 + c);
            *reinterpret_cast<float4*>(sB + r * 36 + c) = v;
        }
        __syncthreads();

        #pragma unroll
        for (int kk = 0; kk < 4; kk++) {
            const int kb = kk * 8;
            uint32_t a[2][4];
            #pragma unroll
            for (int mt = 0; mt < 2; mt++) {
                int r0 = wm * 32 + mt * 16 + gid;
                a[mt][0] = __float_as_uint(sA[r0 * 36 + kb + tig]);
                a[mt][1] = __float_as_uint(sA[(r0 + 8) * 36 + kb + tig]);
                a[mt][2] = __float_as_uint(sA[r0 * 36 + kb + tig + 4]);
                a[mt][3] = __float_as_uint(sA[(r0 + 8) * 36 + kb + tig + 4]);
            }
            uint32_t b[4][2];
            #pragma unroll
            for (int nt = 0; nt < 4; nt++) {
                int n0 = wn * 32 + nt * 8 + gid;
                b[nt][0] = __float_as_uint(sB[n0 * 36 + kb + tig]);
                b[nt][1] = __float_as_uint(sB[n0 * 36 + kb + tig + 4]);
            }
            #pragma unroll
            for (int mt = 0; mt < 2; mt++)
                #pragma unroll
                for (int nt = 0; nt < 4; nt++)
                    mma_tf32(acc[mt][nt], a[mt], b[nt]);
        }
        __syncthreads();
    }

    // stage tile and write coalesced
    float* gsm = sm;  // [128][68]
    #pragma unroll
    for (int mt = 0; mt < 2; mt++)
        #pragma unroll
        for (int nt = 0; nt < 4; nt++) {
            int r0 = wm * 32 + mt * 16 + gid;
            int c0 = wn * 32 + nt * 8 + tig * 2;
            gsm[r0 * 68 + c0]           = acc[mt][nt][0];
            gsm[r0 * 68 + c0 + 1]       = acc[mt][nt][1];
            gsm[(r0 + 8) * 68 + c0]     = acc[mt][nt][2];
            gsm[(r0 + 8) * 68 + c0 + 1] = acc[mt][nt][3];
        }
    __syncthreads();
    #pragma unroll
    for (int it = 0; it < 8; it++) {
        int idx = tid + it * 256;
        int r = idx >> 4, c4 = idx & 15;
        float4 v = *reinterpret_cast<float4*>(gsm + r * 68 + c4 * 4);
        *reinterpret_cast<float4*>(g_xW + (size_t)(mb + r) * Gn + nbase + c4 * 4) = v;
    }
}

// ---------------- Persistent recurrent kernel ----------------
// grid = 128 CTAs (co-resident), 256 threads. CTA owns 8 hidden cols
// (32 gate rows). W_hh slice lives in smem for all 128 timesteps.
// thread tid == batch index b; c/h state in registers.
#define SWPITCH 1028
#define SAPITCH 36
#define SA_ELEMS (256*SAPITCH)
#define REC_SMEM ((32*SWPITCH + 2*SA_ELEMS)*4)

template<bool L0>
__global__ void __launch_bounds__(256, 1) rec_kernel(int layer,
                                                     const float* __restrict__ bias,
                                                     const float* __restrict__ Wih0,
                                                     const int* __restrict__ tokens,
                                                     const int* __restrict__ lengths,
                                                     float* __restrict__ out) {
    extern __shared__ float sm[];
    float* sW = sm;                       // [32][1028] weights, resident
    float* sA = sm + 32 * SWPITCH;        // 2 x [256][36] h-chunk buffers
    __shared__ float sBias[32];

    const int tid  = threadIdx.x;
    const int lane = tid & 31, wid = tid >> 5;
    const int gid = lane >> 2, tig = lane & 3;
    const int jbase = blockIdx.x * 8;

    const float* Whh = g_Whh + (size_t)layer * NW;

    // load resident weight slice: smem row r -> weight row (r>>3)*1024 + jbase + (r&7)
    #pragma unroll
    for (int it = 0; it < 32; it++) {
        int idx = tid + it * 256;
        int r = idx >> 8, c4 = idx & 255;
        int wr = ((r >> 3) << 10) + jbase + (r & 7);
        float4 v = *reinterpret_cast<const float4*>(Whh + (size_t)wr * Hn + c4 * 4);
        *reinterpret_cast<float4*>(sW + r * SWPITCH + c4 * 4) = v;
    }
    if (tid < 32)
        sBias[tid] = bias[((tid >> 3) << 10) + jbase + (tid & 7)];

    float creg[8], hreg[8];
    #pragma unroll
    for (int j = 0; j < 8; j++) { creg[j] = 0.f; hreg[j] = 0.f; }
    const int b = tid;
    const int lenb = lengths[b];
    __syncthreads();

    for (int t = 0; t < Tn; t++) {
        const float* hin = g_hio[t & 1];

        // prefetch chunk 0
        #pragma unroll
        for (int it = 0; it < 8; it++) {
            int idx = tid + it * 256;
            int r = idx >> 3, c4 = idx & 7;
            cpasync16(sA + r * SAPITCH + c4 * 4, hin + (size_t)r * Hn + c4 * 4);
        }
        asm volatile("cp.async.commit_group;\n");

        float acc[2][4][4];
        #pragma unroll
        for (int a0 = 0; a0 < 2; a0++)
            #pragma unroll
            for (int a1 = 0; a1 < 4; a1++)
                #pragma unroll
                for (int a2 = 0; a2 < 4; a2++) acc[a0][a1][a2] = 0.f;

        for (int kc = 0; kc < 32; kc++) {
            if (kc < 31) {
                float* dst = sA + ((kc + 1) & 1) * SA_ELEMS;
                const float* src = hin + (kc + 1) * 32;
                #pragma unroll
                for (int it = 0; it < 8; it++) {
                    int idx = tid + it * 256;
                    int r = idx >> 3, c4 = idx & 7;
                    cpasync16(dst + r * SAPITCH + c4 * 4, src + (size_t)r * Hn + c4 * 4);
                }
                asm volatile("cp.async.commit_group;\n");
                asm volatile("cp.async.wait_group 1;\n");
            } else {
                asm volatile("cp.async.wait_group 0;\n");
            }
            __syncthreads();

            const float* A = sA + (kc & 1) * SA_ELEMS;
            const int kw0 = kc * 32;
            #pragma unroll
            for (int kk = 0; kk < 4; kk++) {
                const int kb = kk * 8;
                uint32_t a[2][4];
                #pragma unroll
                for (int mt = 0; mt < 2; mt++) {
                    int r0 = wid * 32 + mt * 16 + gid;
                    a[mt][0] = __float_as_uint(A[r0 * SAPITCH + kb + tig]);
                    a[mt][1] = __float_as_uint(A[(r0 + 8) * SAPITCH + kb + tig]);
                    a[mt][2] = __float_as_uint(A[r0 * SAPITCH + kb + tig + 4]);
                    a[mt][3] = __float_as_uint(A[(r0 + 8) * SAPITCH + kb + tig + 4]);
                }
                uint32_t bfr[4][2];
                #pragma unroll
                for (int nt = 0; nt < 4; nt++) {
                    int n0 = nt * 8 + gid;
                    bfr[nt][0] = __float_as_uint(sW[n0 * SWPITCH + kw0 + kb + tig]);
                    bfr[nt][1] = __float_as_uint(sW[n0 * SWPITCH + kw0 + kb + tig + 4]);
                }
                #pragma unroll
                for (int mt = 0; mt < 2; mt++)
                    #pragma unroll
                    for (int nt = 0; nt < 4; nt++)
                        mma_tf32(acc[mt][nt], a[mt], bfr[nt]);
            }
            __syncthreads();
        }

        // gate exchange: gsm[n][257] over batch; aliases sA buffer 0 (safe: synced)
        float* gsm = sA;
        #pragma unroll
        for (int mt = 0; mt < 2; mt++)
            #pragma unroll
            for (int nt = 0; nt < 4; nt++) {
                int r0 = wid * 32 + mt * 16 + gid;
                int c0 = nt * 8 + tig * 2;
                gsm[c0 * 257 + r0]             = acc[mt][nt][0];
                gsm[(c0 + 1) * 257 + r0]       = acc[mt][nt][1];
                gsm[c0 * 257 + r0 + 8]         = acc[mt][nt][2];
                gsm[(c0 + 1) * 257 + r0 + 8]   = acc[mt][nt][3];
            }
        __syncthreads();

        // pointwise: thread handles batch b, 8 hidden cols
        float gt[4][8];
        if (L0) {
            int tok = tokens[b * Tn + t];
            #pragma unroll
            for (int g = 0; g < 4; g++)
                #pragma unroll
                for (int jl = 0; jl < 8; jl++) {
                    int n = g * 8 + jl;
                    gt[g][jl] = gsm[n * 257 + b] + sBias[n]
                              + Wih0[(size_t)((g << 10) + jbase + jl) * Vn + tok];
                }
        } else {
            const float* xw = g_xW + (size_t)(t * Bn + b) * Gn + jbase;
            #pragma unroll
            for (int g = 0; g < 4; g++) {
                float4 v0 = *reinterpret_cast<const float4*>(xw + (g << 10));
                float4 v1 = *reinterpret_cast<const float4*>(xw + (g << 10) + 4);
                gt[g][0] = v0.x; gt[g][1] = v0.y; gt[g][2] = v0.z; gt[g][3] = v0.w;
                gt[g][4] = v1.x; gt[g][5] = v1.y; gt[g][6] = v1.z; gt[g][7] = v1.w;
                #pragma unroll
                for (int jl = 0; jl < 8; jl++) {
                    int n = g * 8 + jl;
                    gt[g][jl] += gsm[n * 257 + b] + sBias[n];
                }
            }
        }

        float hro[8], hso[8];
        const bool msk = (t < lenb);
        #pragma unroll
        for (int jl = 0; jl < 8; jl++) {
            float i = sigmoidf_(gt[0][jl]);
            float f = sigmoidf_(gt[1][jl]);
            float g = tanhf(gt[2][jl]);
            float o = sigmoidf_(gt[3][jl]);
            float cn = f * creg[jl] + i * g;
            float hn = o * tanhf(cn);
            float hv = msk ? hn : hreg[jl];
            float cv = msk ? cn : creg[jl];
            creg[jl] = cv; hreg[jl] = hv;
            hro[jl] = tf32r(hv);
            hso[jl] = hv;
        }
        float* hioOut = g_hio[(t + 1) & 1] + (size_t)b * Hn + jbase;
        float* hsOut  = g_hs[layer & 1] + (size_t)t * BH + (size_t)b * Hn + jbase;
        *reinterpret_cast<float4*>(hioOut)     = make_float4(hro[0], hro[1], hro[2], hro[3]);
        *reinterpret_cast<float4*>(hioOut + 4) = make_float4(hro[4], hro[5], hro[6], hro[7]);
        *reinterpret_cast<float4*>(hsOut)      = make_float4(hso[0], hso[1], hso[2], hso[3]);
        *reinterpret_cast<float4*>(hsOut + 4)  = make_float4(hso[4], hso[5], hso[6], hso[7]);

        // grid barrier (monotonic counter; 128 co-resident CTAs)
        __threadfence();
        __syncthreads();
        if (tid == 0) {
            atomicAdd(&g_bar, 1u);
            unsigned tgt = 128u * (unsigned)(t + 1);
            unsigned v;
            do {
                asm volatile("ld.acquire.gpu.u32 %0, [%1];" : "=r"(v) : "l"(&g_bar));
                if (v < tgt) __nanosleep(64);
            } while (v < tgt);
        }
        __syncthreads();
    }

    // final h/c -> output (replaces copy_final)
    float* oh = out + LOGN + (size_t)layer * BH + (size_t)b * Hn + jbase;
    float* oc = out + LOGN + (size_t)3 * BH + (size_t)layer * BH + (size_t)b * Hn + jbase;
    *reinterpret_cast<float4*>(oh)     = make_float4(hreg[0], hreg[1], hreg[2], hreg[3]);
    *reinterpret_cast<float4*>(oh + 4) = make_float4(hreg[4], hreg[5], hreg[6], hreg[7]);
    *reinterpret_cast<float4*>(oc)     = make_float4(creg[0], creg[1], creg[2], creg[3]);
    *reinterpret_cast<float4*>(oc + 4) = make_float4(creg[4], creg[5], creg[6], creg[7]);
}

// ---------------- Output head: logits = hs . W_out^T + b_out (masked) --------
__global__ void __launch_bounds__(256) logits_kernel(const float* __restrict__ bout,
                                                     const int* __restrict__ lengths,
                                                     float* __restrict__ out) {
    int gw   = (blockIdx.x * blockDim.x + threadIdx.x) >> 5;
    int lane = threadIdx.x & 31;
    const float* hs = g_hs[0];            // layer-2 output (2&1 == 0)
    int row0 = gw * 4;
    const float* hp = hs + (size_t)row0 * Hn;
    float acc0 = 0.f, acc1 = 0.f, acc2 = 0.f, acc3 = 0.f;

    for (int k0 = 0; k0 < Hn; k0 += 32) {
        float h0 = hp[k0 + lane];
        float h1 = hp[Hn + k0 + lane];
        float h2 = hp[2 * Hn + k0 + lane];
        float h3 = hp[3 * Hn + k0 + lane];
        #pragma unroll
        for (int i = 0; i < 32; i++) {
            float w = g_WoutT[(k0 + i) * Vn + lane];
            acc0 += __shfl_sync(0xffffffffu, h0, i) * w;
            acc1 += __shfl_sync(0xffffffffu, h1, i) * w;
            acc2 += __shfl_sync(0xffffffffu, h2, i) * w;
            acc3 += __shfl_sync(0xffffffffu, h3, i) * w;
        }
    }
    float bo = bout[lane];
    float accs[4] = {acc0, acc1, acc2, acc3};
    #pragma unroll
    for (int r = 0; r < 4; r++) {
        int row = row0 + r;
        int t = row >> 8;
        int b = row & 255;
        float v = (t < lengths[b]) ? (accs[r] + bo) : 0.f;
        out[((size_t)b * Tn + t) * Vn + lane] = v;
    }
}

// ---------------- Launch ----------------
extern "C" void kernel_launch(void* const* d_in, const int* in_sizes, int n_in,
                              void* d_out, int out_size) {
    const int*   tokens  = (const int*)d_in[0];
    const int*   lengths = (const int*)d_in[1];
    const float* Wih0    = (const float*)d_in[2];
    const float* Whh0    = (const float*)d_in[3];
    const float* b0      = (const float*)d_in[4];
    const float* Wih_r   = (const float*)d_in[5];
    const float* Whh_r   = (const float*)d_in[6];
    const float* b_r     = (const float*)d_in[7];
    const float* Wout    = (const float*)d_in[8];
    const float* bout    = (const float*)d_in[9];
    float* out = (float*)d_out;

    static bool attrDone = false;
    if (!attrDone) {
        cudaFuncSetAttribute(rec_kernel<true>,
                             cudaFuncAttributeMaxDynamicSharedMemorySize, REC_SMEM);
        cudaFuncSetAttribute(rec_kernel<false>,
                             cudaFuncAttributeMaxDynamicSharedMemorySize, REC_SMEM);
        attrDone = true;
    }

    prep_kernel<<<1024, 256>>>(Whh0, Wih_r, Whh_r, Wout);

    for (int l = 0; l < 3; l++) {
        zero_state<<<1024, 256>>>();
        if (l > 0) gemmA<<<dim3(64, 256), 256>>>(l);
        const float* bias = (l == 0) ? b0 : (b_r + (size_t)(l - 1) * Gn);
        if (l == 0)
            rec_kernel<true><<<128, 256, REC_SMEM>>>(l, bias, Wih0, tokens, lengths, out);
        else
            rec_kernel<false><<<128, 256, REC_SMEM>>>(l, bias, Wih0, tokens, lengths, out);
    }
    logits_kernel<<<1024, 256>>>(bout, lengths, out);
}

// round 6
// speedup vs baseline: 1.8712x; 1.1997x over previous
#include <cuda_runtime.h>
#include <cstdint>

// ---------------- Problem constants ----------------
#define Bn 256
#define Tn 128
#define Hn 1024
#define Vn 32
#define Gn 4096              // 4*H
#define BH (Bn*Hn)           // 262144
#define THB (Tn*BH)          // 33554432
#define NW (Gn*Hn)           // 4194304 (one weight matrix)
#define MROWS (Tn*Bn)        // 32768 rows of the big input GEMM
#define LOGN (Bn*Tn*Vn)      // 1048576 logits floats

// ---------------- Device scratch (allocation-free) ----------------
__device__ float g_Whh[3*NW];      // tf32-rounded recurrent weights
__device__ float g_Wih[2*NW];      // tf32-rounded input weights (layers 1..2)
__device__ float g_hs[2][THB];     // ping-pong full-precision hidden sequences
__device__ float g_xW[(size_t)MROWS*Gn]; // precomputed input projection
__device__ float g_hio[2][BH];     // ping-pong tf32-rounded h (GEMM operand)
__device__ float g_WoutT[Hn*Vn];   // W_out transposed [k][v]
__device__ unsigned g_bar;         // grid barrier counter

// ---------------- Helpers ----------------
__device__ __forceinline__ float tf32r(float x) {
    uint32_t u;
    asm("cvt.rna.tf32.f32 %0, %1;" : "=r"(u) : "f"(x));
    return __uint_as_float(u);
}

__device__ __forceinline__ void mma_tf32(float* d, const uint32_t* a, const uint32_t* b) {
    asm volatile(
        "mma.sync.aligned.m16n8k8.row.col.f32.tf32.tf32.f32 "
        "{%0,%1,%2,%3},{%4,%5,%6,%7},{%8,%9},{%0,%1,%2,%3};\n"
        : "+f"(d[0]), "+f"(d[1]), "+f"(d[2]), "+f"(d[3])
        : "r"(a[0]), "r"(a[1]), "r"(a[2]), "r"(a[3]), "r"(b[0]), "r"(b[1]));
}

__device__ __forceinline__ void cpasync16(float* dst, const float* src) {
    uint32_t d = (uint32_t)__cvta_generic_to_shared(dst);
    asm volatile("cp.async.cg.shared.global [%0], [%1], 16;\n" :: "r"(d), "l"(src));
}

__device__ __forceinline__ float sigmoidf_(float x) {
    return 1.0f / (1.0f + __expf(-x));
}

// ---------------- Prep: round weights to tf32, transpose W_out ----------------
__global__ void prep_kernel(const float* __restrict__ Whh0,
                            const float* __restrict__ Wih_rest,
                            const float* __restrict__ Whh_rest,
                            const float* __restrict__ Wout) {
    int i = blockIdx.x * blockDim.x + threadIdx.x;
    int stride = gridDim.x * blockDim.x;
    for (int idx = i; idx < NW; idx += stride)
        g_Whh[idx] = tf32r(Whh0[idx]);
    for (int idx = i; idx < 2 * NW; idx += stride) {
        g_Whh[NW + idx] = tf32r(Whh_rest[idx]);
        g_Wih[idx]      = tf32r(Wih_rest[idx]);
    }
    for (int idx = i; idx < Hn * Vn; idx += stride) {
        int v = idx >> 10, k = idx & 1023;
        g_WoutT[k * Vn + v] = Wout[idx];
    }
}

// ---------------- Reset h state + barrier before each recurrent phase --------
__global__ void zero_state() {
    int i = blockIdx.x * blockDim.x + threadIdx.x;
    if (i == 0) g_bar = 0;
    if (i < BH) { g_hio[0][i] = 0.f; g_hio[1][i] = 0.f; }
}

// ---------------- Phase A: xW = hs_prev . Wih^T (layers 1..2), no bias -------
// grid (32, 256): bx = 128-col n-tile, by = 128-row m-tile. 256 threads.
// Warp grid 4(m) x 2(n); warp tile 32x64. Direct float2 stores for C.
__global__ void __launch_bounds__(256) gemmA(int l) {
    __shared__ float sA[128 * 36];
    __shared__ float sB[128 * 36];

    const int tid  = threadIdx.x;
    const int lane = tid & 31, wid = tid >> 5;
    const int wm = wid & 3, wn = wid >> 2;
    const int gid = lane >> 2, tig = lane & 3;
    const int nbase = blockIdx.x * 128;
    const int mb = blockIdx.y * 128;

    const float* A  = g_hs[(l - 1) & 1] + (size_t)mb * Hn;
    const float* Bw = g_Wih + (size_t)(l - 1) * NW + (size_t)nbase * Hn;

    float acc[2][8][4];
    #pragma unroll
    for (int a0 = 0; a0 < 2; a0++)
        #pragma unroll
        for (int a1 = 0; a1 < 8; a1++)
            #pragma unroll
            for (int a2 = 0; a2 < 4; a2++) acc[a0][a1][a2] = 0.f;

    for (int k0 = 0; k0 < Hn; k0 += 32) {
        #pragma unroll
        for (int it = 0; it < 4; it++) {
            int idx = tid + it * 256;
            int r = idx >> 3, c = (idx & 7) * 4;
            float4 va = *reinterpret_cast<const float4*>(A + (size_t)r * Hn + k0 + c);
            *reinterpret_cast<float4*>(sA + r * 36 + c) = va;
            float4 vb = *reinterpret_cast<const float4*>(Bw + (size_t)r * Hn + k0 + c);
            *reinterpret_cast<float4*>(sB + r * 36 + c) = vb;
        }
        __syncthreads();

        #pragma unroll
        for (int kk = 0; kk < 4; kk++) {
            const int kb = kk * 8;
            uint32_t a[2][4];
            #pragma unroll
            for (int mt = 0; mt < 2; mt++) {
                int r0 = wm * 32 + mt * 16 + gid;
                a[mt][0] = __float_as_uint(sA[r0 * 36 + kb + tig]);
                a[mt][1] = __float_as_uint(sA[(r0 + 8) * 36 + kb + tig]);
                a[mt][2] = __float_as_uint(sA[r0 * 36 + kb + tig + 4]);
                a[mt][3] = __float_as_uint(sA[(r0 + 8) * 36 + kb + tig + 4]);
            }
            uint32_t b[8][2];
            #pragma unroll
            for (int nt = 0; nt < 8; nt++) {
                int n0 = wn * 64 + nt * 8 + gid;
                b[nt][0] = __float_as_uint(sB[n0 * 36 + kb + tig]);
                b[nt][1] = __float_as_uint(sB[n0 * 36 + kb + tig + 4]);
            }
            #pragma unroll
            for (int mt = 0; mt < 2; mt++)
                #pragma unroll
                for (int nt = 0; nt < 8; nt++)
                    mma_tf32(acc[mt][nt], a[mt], b[nt]);
        }
        __syncthreads();
    }

    // direct global stores (float2, 32B-sector friendly)
    #pragma unroll
    for (int mt = 0; mt < 2; mt++)
        #pragma unroll
        for (int nt = 0; nt < 8; nt++) {
            int r0 = mb + wm * 32 + mt * 16 + gid;
            int c0 = nbase + wn * 64 + nt * 8 + tig * 2;
            *reinterpret_cast<float2*>(g_xW + (size_t)r0 * Gn + c0) =
                make_float2(acc[mt][nt][0], acc[mt][nt][1]);
            *reinterpret_cast<float2*>(g_xW + (size_t)(r0 + 8) * Gn + c0) =
                make_float2(acc[mt][nt][2], acc[mt][nt][3]);
        }
}

// ---------------- Persistent recurrent kernel ----------------
// grid = 128 CTAs (co-resident), 256 threads. CTA owns 8 hidden cols
// (32 gate rows). W_hh slice resident in smem for all 128 timesteps.
// Each WARP owns a 32-row batch slice with a private 2-stage cp.async
// pipeline -- no CTA barriers inside the K loop.
#define SWPITCH 1028
#define SAW (32*36)               // one per-warp A stage: 32 rows x 36 pitch
#define REC_SMEM ((32*SWPITCH + 8*2*SAW)*4)

template<bool L0>
__global__ void __launch_bounds__(256, 1) rec_kernel(int layer,
                                                     const float* __restrict__ bias,
                                                     const float* __restrict__ Wih0,
                                                     const int* __restrict__ tokens,
                                                     const int* __restrict__ lengths,
                                                     float* __restrict__ out) {
    extern __shared__ float sm[];
    float* sW = sm;                       // [32][1028] weights, resident
    float* sA = sm + 32 * SWPITCH;        // 8 warps x 2 stages x [32][36]
    __shared__ float sBias[32];

    const int tid  = threadIdx.x;
    const int lane = tid & 31, wid = tid >> 5;
    const int gid = lane >> 2, tig = lane & 3;
    const int jbase = blockIdx.x * 8;

    const float* Whh = g_Whh + (size_t)layer * NW;

    // load resident weight slice: smem row r -> weight row (r>>3)*1024 + jbase + (r&7)
    #pragma unroll
    for (int it = 0; it < 32; it++) {
        int idx = tid + it * 256;
        int r = idx >> 8, c4 = idx & 255;
        int wr = ((r >> 3) << 10) + jbase + (r & 7);
        float4 v = *reinterpret_cast<const float4*>(Whh + (size_t)wr * Hn + c4 * 4);
        *reinterpret_cast<float4*>(sW + r * SWPITCH + c4 * 4) = v;
    }
    if (tid < 32)
        sBias[tid] = bias[((tid >> 3) << 10) + jbase + (tid & 7)];

    float creg[8], hreg[8];
    #pragma unroll
    for (int j = 0; j < 8; j++) { creg[j] = 0.f; hreg[j] = 0.f; }
    const int b = tid;
    const int lenb = lengths[b];
    float* sAw = sA + wid * 2 * SAW;      // this warp's two-stage buffer
    __syncthreads();

    for (int t = 0; t < Tn; t++) {
        const float* hwarp = g_hio[t & 1] + (size_t)(wid * 32) * Hn;

        // prefetch chunk 0 (per-warp)
        #pragma unroll
        for (int it = 0; it < 8; it++) {
            int idx = lane + it * 32;
            int r = idx >> 3, c4 = idx & 7;
            cpasync16(sAw + r * 36 + c4 * 4, hwarp + (size_t)r * Hn + c4 * 4);
        }
        asm volatile("cp.async.commit_group;\n");

        float acc[2][4][4];
        #pragma unroll
        for (int a0 = 0; a0 < 2; a0++)
            #pragma unroll
            for (int a1 = 0; a1 < 4; a1++)
                #pragma unroll
                for (int a2 = 0; a2 < 4; a2++) acc[a0][a1][a2] = 0.f;

        for (int kc = 0; kc < 32; kc++) {
            if (kc < 31) {
                float* dst = sAw + ((kc + 1) & 1) * SAW;
                const float* src = hwarp + (kc + 1) * 32;
                #pragma unroll
                for (int it = 0; it < 8; it++) {
                    int idx = lane + it * 32;
                    int r = idx >> 3, c4 = idx & 7;
                    cpasync16(dst + r * 36 + c4 * 4, src + (size_t)r * Hn + c4 * 4);
                }
                asm volatile("cp.async.commit_group;\n");
                asm volatile("cp.async.wait_group 1;\n");
            } else {
                asm volatile("cp.async.wait_group 0;\n");
            }
            __syncwarp();

            const float* A = sAw + (kc & 1) * SAW;
            const int kw0 = kc * 32;
            #pragma unroll
            for (int kk = 0; kk < 4; kk++) {
                const int kb = kk * 8;
                uint32_t a[2][4];
                #pragma unroll
                for (int mt = 0; mt < 2; mt++) {
                    int r0 = mt * 16 + gid;              // warp-local batch row
                    a[mt][0] = __float_as_uint(A[r0 * 36 + kb + tig]);
                    a[mt][1] = __float_as_uint(A[(r0 + 8) * 36 + kb + tig]);
                    a[mt][2] = __float_as_uint(A[r0 * 36 + kb + tig + 4]);
                    a[mt][3] = __float_as_uint(A[(r0 + 8) * 36 + kb + tig + 4]);
                }
                uint32_t bfr[4][2];
                #pragma unroll
                for (int nt = 0; nt < 4; nt++) {
                    int n0 = nt * 8 + gid;
                    bfr[nt][0] = __float_as_uint(sW[n0 * SWPITCH + kw0 + kb + tig]);
                    bfr[nt][1] = __float_as_uint(sW[n0 * SWPITCH + kw0 + kb + tig + 4]);
                }
                #pragma unroll
                for (int mt = 0; mt < 2; mt++)
                    #pragma unroll
                    for (int nt = 0; nt < 4; nt++)
                        mma_tf32(acc[mt][nt], a[mt], bfr[nt]);
            }
            __syncwarp();
        }

        __syncthreads();   // all warps done reading sA before aliasing as gsm

        // gate exchange: gsm[n][257] over batch; aliases sA region
        float* gsm = sA;
        #pragma unroll
        for (int mt = 0; mt < 2; mt++)
            #pragma unroll
            for (int nt = 0; nt < 4; nt++) {
                int r0 = wid * 32 + mt * 16 + gid;
                int c0 = nt * 8 + tig * 2;
                gsm[c0 * 257 + r0]             = acc[mt][nt][0];
                gsm[(c0 + 1) * 257 + r0]       = acc[mt][nt][1];
                gsm[c0 * 257 + r0 + 8]         = acc[mt][nt][2];
                gsm[(c0 + 1) * 257 + r0 + 8]   = acc[mt][nt][3];
            }
        __syncthreads();

        // pointwise: thread handles batch b, 8 hidden cols
        float gt[4][8];
        if (L0) {
            int tok = tokens[b * Tn + t];
            #pragma unroll
            for (int g = 0; g < 4; g++)
                #pragma unroll
                for (int jl = 0; jl < 8; jl++) {
                    int n = g * 8 + jl;
                    gt[g][jl] = gsm[n * 257 + b] + sBias[n]
                              + Wih0[(size_t)((g << 10) + jbase + jl) * Vn + tok];
                }
        } else {
            const float* xw = g_xW + (size_t)(t * Bn + b) * Gn + jbase;
            #pragma unroll
            for (int g = 0; g < 4; g++) {
                float4 v0 = *reinterpret_cast<const float4*>(xw + (g << 10));
                float4 v1 = *reinterpret_cast<const float4*>(xw + (g << 10) + 4);
                gt[g][0] = v0.x; gt[g][1] = v0.y; gt[g][2] = v0.z; gt[g][3] = v0.w;
                gt[g][4] = v1.x; gt[g][5] = v1.y; gt[g][6] = v1.z; gt[g][7] = v1.w;
                #pragma unroll
                for (int jl = 0; jl < 8; jl++) {
                    int n = g * 8 + jl;
                    gt[g][jl] += gsm[n * 257 + b] + sBias[n];
                }
            }
        }

        float hro[8], hso[8];
        const bool msk = (t < lenb);
        #pragma unroll
        for (int jl = 0; jl < 8; jl++) {
            float i = sigmoidf_(gt[0][jl]);
            float f = sigmoidf_(gt[1][jl]);
            float g = tanhf(gt[2][jl]);
            float o = sigmoidf_(gt[3][jl]);
            float cn = f * creg[jl] + i * g;
            float hn = o * tanhf(cn);
            float hv = msk ? hn : hreg[jl];
            float cv = msk ? cn : creg[jl];
            creg[jl] = cv; hreg[jl] = hv;
            hro[jl] = tf32r(hv);
            hso[jl] = hv;
        }
        float* hioOut = g_hio[(t + 1) & 1] + (size_t)b * Hn + jbase;
        float* hsOut  = g_hs[layer & 1] + (size_t)t * BH + (size_t)b * Hn + jbase;
        *reinterpret_cast<float4*>(hioOut)     = make_float4(hro[0], hro[1], hro[2], hro[3]);
        *reinterpret_cast<float4*>(hioOut + 4) = make_float4(hro[4], hro[5], hro[6], hro[7]);
        *reinterpret_cast<float4*>(hsOut)      = make_float4(hso[0], hso[1], hso[2], hso[3]);
        *reinterpret_cast<float4*>(hsOut + 4)  = make_float4(hso[4], hso[5], hso[6], hso[7]);

        // grid barrier (monotonic counter; 128 co-resident CTAs; short backoff)
        __threadfence();
        __syncthreads();
        if (tid == 0) {
            atomicAdd(&g_bar, 1u);
            unsigned tgt = 128u * (unsigned)(t + 1);
            unsigned v;
            do {
                asm volatile("ld.acquire.gpu.u32 %0, [%1];" : "=r"(v) : "l"(&g_bar));
                if (v < tgt) __nanosleep(32);
            } while (v < tgt);
        }
        __syncthreads();
    }

    // final h/c -> output
    float* oh = out + LOGN + (size_t)layer * BH + (size_t)b * Hn + jbase;
    float* oc = out + LOGN + (size_t)3 * BH + (size_t)layer * BH + (size_t)b * Hn + jbase;
    *reinterpret_cast<float4*>(oh)     = make_float4(hreg[0], hreg[1], hreg[2], hreg[3]);
    *reinterpret_cast<float4*>(oh + 4) = make_float4(hreg[4], hreg[5], hreg[6], hreg[7]);
    *reinterpret_cast<float4*>(oc)     = make_float4(creg[0], creg[1], creg[2], creg[3]);
    *reinterpret_cast<float4*>(oc + 4) = make_float4(creg[4], creg[5], creg[6], creg[7]);
}

// ---------------- Output head: logits = hs . W_out^T + b_out (masked) --------
__global__ void __launch_bounds__(256) logits_kernel(const float* __restrict__ bout,
                                                     const int* __restrict__ lengths,
                                                     float* __restrict__ out) {
    int gw   = (blockIdx.x * blockDim.x + threadIdx.x) >> 5;
    int lane = threadIdx.x & 31;
    const float* hs = g_hs[0];            // layer-2 output (2&1 == 0)
    int row0 = gw * 4;
    const float* hp = hs + (size_t)row0 * Hn;
    float acc0 = 0.f, acc1 = 0.f, acc2 = 0.f, acc3 = 0.f;

    for (int k0 = 0; k0 < Hn; k0 += 32) {
        float h0 = hp[k0 + lane];
        float h1 = hp[Hn + k0 + lane];
        float h2 = hp[2 * Hn + k0 + lane];
        float h3 = hp[3 * Hn + k0 + lane];
        #pragma unroll
        for (int i = 0; i < 32; i++) {
            float w = g_WoutT[(k0 + i) * Vn + lane];
            acc0 += __shfl_sync(0xffffffffu, h0, i) * w;
            acc1 += __shfl_sync(0xffffffffu, h1, i) * w;
            acc2 += __shfl_sync(0xffffffffu, h2, i) * w;
            acc3 += __shfl_sync(0xffffffffu, h3, i) * w;
        }
    }
    float bo = bout[lane];
    float accs[4] = {acc0, acc1, acc2, acc3};
    #pragma unroll
    for (int r = 0; r < 4; r++) {
        int row = row0 + r;
        int t = row >> 8;
        int b = row & 255;
        float v = (t < lengths[b]) ? (accs[r] + bo) : 0.f;
        out[((size_t)b * Tn + t) * Vn + lane] = v;
    }
}

// ---------------- Launch ----------------
extern "C" void kernel_launch(void* const* d_in, const int* in_sizes, int n_in,
                              void* d_out, int out_size) {
    const int*   tokens  = (const int*)d_in[0];
    const int*   lengths = (const int*)d_in[1];
    const float* Wih0    = (const float*)d_in[2];
    const float* Whh0    = (const float*)d_in[3];
    const float* b0      = (const float*)d_in[4];
    const float* Wih_r   = (const float*)d_in[5];
    const float* Whh_r   = (const float*)d_in[6];
    const float* b_r     = (const float*)d_in[7];
    const float* Wout    = (const float*)d_in[8];
    const float* bout    = (const float*)d_in[9];
    float* out = (float*)d_out;

    static bool attrDone = false;
    if (!attrDone) {
        cudaFuncSetAttribute(rec_kernel<true>,
                             cudaFuncAttributeMaxDynamicSharedMemorySize, REC_SMEM);
        cudaFuncSetAttribute(rec_kernel<false>,
                             cudaFuncAttributeMaxDynamicSharedMemorySize, REC_SMEM);
        attrDone = true;
    }

    prep_kernel<<<1024, 256>>>(Whh0, Wih_r, Whh_r, Wout);

    for (int l = 0; l < 3; l++) {
        zero_state<<<1024, 256>>>();
        if (l > 0) gemmA<<<dim3(32, 256), 256>>>(l);
        const float* bias = (l == 0) ? b0 : (b_r + (size_t)(l - 1) * Gn);
        if (l == 0)
            rec_kernel<true><<<128, 256, REC_SMEM>>>(l, bias, Wih0, tokens, lengths, out);
        else
            rec_kernel<false><<<128, 256, REC_SMEM>>>(l, bias, Wih0, tokens, lengths, out);
    }
    logits_kernel<<<1024, 256>>>(bout, lengths, out);
}